// round 11
// baseline (speedup 1.0000x reference)
#include <cuda_runtime.h>
#include <cstdint>

#define N_NODES_C 100000
#define N_EDGES_C 1600000
#define D_FEAT 64
#define D_VEC  (D_FEAT / 4)
#define CAP 64            // per-node bucket capacity (Poisson(16): P(>64) ~ 1e-20)
#define OVF_CAP 8192
#define WEIGHT 0.15f

// packed f32x2 add (Blackwell): one instruction adds two floats in a 64b pair
#define ADD_F32X2(out, a, b) \
    asm("add.rn.f32x2 %0, %1, %2;" : "=l"(out) : "l"(a), "l"(b))

// -------------------- device scratch (static, zero-initialized) ------------
// Invariants (hold on every call, for this fixed input):
//  * g_count[] is ZERO at entry (zero-init on call 1; aggregate resets after).
//  * bucket slots [deg(node), CAP) are NEVER written (deg identical each call),
//    so they stay zero forever -> reading b[0..7] before deg is known is safe.
__device__ int g_count[N_NODES_C];
__device__ int g_bucket[(size_t)N_NODES_C * CAP];   // src indices grouped by dst
__device__ int g_ovf_edges[OVF_CAP];
__device__ int g_ovf_count;

// -------------------- 1) bucket fill (4 edges per thread) ------------------
__global__ void appr_fill_kernel(const int* __restrict__ ei) {
    int t = blockIdx.x * blockDim.x + threadIdx.x;
    int e0 = t * 4;
    if (e0 >= N_EDGES_C) return;

    int4 src = *reinterpret_cast<const int4*>(ei + e0);
    int4 dst = *reinterpret_cast<const int4*>(ei + N_EDGES_C + e0);

    // 4 independent atomics in flight, then 4 writes
    int p0 = atomicAdd(&g_count[dst.x], 1);
    int p1 = atomicAdd(&g_count[dst.y], 1);
    int p2 = atomicAdd(&g_count[dst.z], 1);
    int p3 = atomicAdd(&g_count[dst.w], 1);

    if (p0 < CAP) g_bucket[(size_t)dst.x * CAP + p0] = src.x;
    else { int o = atomicAdd(&g_ovf_count, 1); if (o < OVF_CAP) g_ovf_edges[o] = e0; }
    if (p1 < CAP) g_bucket[(size_t)dst.y * CAP + p1] = src.y;
    else { int o = atomicAdd(&g_ovf_count, 1); if (o < OVF_CAP) g_ovf_edges[o] = e0 + 1; }
    if (p2 < CAP) g_bucket[(size_t)dst.z * CAP + p2] = src.z;
    else { int o = atomicAdd(&g_ovf_count, 1); if (o < OVF_CAP) g_ovf_edges[o] = e0 + 2; }
    if (p3 < CAP) g_bucket[(size_t)dst.w * CAP + p3] = src.w;
    else { int o = atomicAdd(&g_ovf_count, 1); if (o < OVF_CAP) g_ovf_edges[o] = e0 + 3; }
}

// -------------------- 2) gather-side aggregate ------------------------------
// One warp per node, lane owns a float2 = one 64-bit f32x2 pack.
// R7 structure (pipelined index prefetch, predicated tail) with the reduction
// tree done in packed f32x2 (half the add instructions) and a 6-block/SM
// occupancy target.
__global__ void __launch_bounds__(256, 6)
appr_aggregate_kernel(const unsigned long long* __restrict__ x2u,
                      float2* __restrict__ out2,
                      const int* __restrict__ ei) {
    int warp = (blockIdx.x * blockDim.x + threadIdx.x) >> 5;
    int lane = threadIdx.x & 31;
    if (warp >= N_NODES_C) return;
    int node = warp;

    const int* b = &g_bucket[(size_t)node * CAP];

    // ---- concurrent prologue loads (all independent) ----
    int4 s0 = *reinterpret_cast<const int4*>(b);        // chunk-0 indices
    int4 s1 = *reinterpret_cast<const int4*>(b + 4);    // (safe: slots >= deg are 0)
    int deg = g_count[node];
    unsigned long long xv = __ldg(&x2u[(size_t)node * 32 + lane]);   // own row

    int degc = deg > CAP ? CAP : deg;

    unsigned long long acc = 0ull;   // f32x2 {0.0f, 0.0f}

    if (degc > 0) {
        int j = 0;
        while (true) {
            int4 c0 = s0, c1 = s1;
            int next = j + 8;
            if (next < degc) {
                // prefetch next chunk's indices BEFORE this chunk's gathers
                s0 = *reinterpret_cast<const int4*>(b + next);
                s1 = *reinterpret_cast<const int4*>(b + next + 4);
            }

            if (next <= degc) {
                // full chunk: 8 unconditional gathers (64b packs)
                unsigned long long u0 = __ldg(&x2u[(size_t)c0.x * 32 + lane]);
                unsigned long long u1 = __ldg(&x2u[(size_t)c0.y * 32 + lane]);
                unsigned long long u2 = __ldg(&x2u[(size_t)c0.z * 32 + lane]);
                unsigned long long u3 = __ldg(&x2u[(size_t)c0.w * 32 + lane]);
                unsigned long long u4 = __ldg(&x2u[(size_t)c1.x * 32 + lane]);
                unsigned long long u5 = __ldg(&x2u[(size_t)c1.y * 32 + lane]);
                unsigned long long u6 = __ldg(&x2u[(size_t)c1.z * 32 + lane]);
                unsigned long long u7 = __ldg(&x2u[(size_t)c1.w * 32 + lane]);
                unsigned long long t01, t23, t45, t67, t03, t47, t07;
                ADD_F32X2(t01, u0, u1);
                ADD_F32X2(t23, u2, u3);
                ADD_F32X2(t45, u4, u5);
                ADD_F32X2(t67, u6, u7);
                ADD_F32X2(t03, t01, t23);
                ADD_F32X2(t47, t45, t67);
                ADD_F32X2(t07, t03, t47);
                ADD_F32X2(acc, acc, t07);
            } else {
                // partial last chunk: predicated gathers (indices already loaded)
                int rem = degc - j;                     // 1..7
                int ids[8] = { c0.x, c0.y, c0.z, c0.w, c1.x, c1.y, c1.z, c1.w };
                unsigned long long u[8];
                #pragma unroll
                for (int k = 0; k < 8; k++) {
                    if (k < rem) u[k] = __ldg(&x2u[(size_t)ids[k] * 32 + lane]);
                    else         u[k] = 0ull;
                }
                unsigned long long t01, t23, t45, t67, t03, t47, t07;
                ADD_F32X2(t01, u[0], u[1]);
                ADD_F32X2(t23, u[2], u[3]);
                ADD_F32X2(t45, u[4], u[5]);
                ADD_F32X2(t67, u[6], u[7]);
                ADD_F32X2(t03, t01, t23);
                ADD_F32X2(t47, t45, t67);
                ADD_F32X2(t07, t03, t47);
                ADD_F32X2(acc, acc, t07);
            }
            j = next;
            if (j >= degc) break;
        }
    }

    float2 accf;
    accf.x = __uint_as_float((unsigned)(acc & 0xffffffffull));
    accf.y = __uint_as_float((unsigned)(acc >> 32));

    // overflow contributions (g_ovf_count == 0 on this data: one broadcast ld)
    int ovf = g_ovf_count;
    if (ovf > 0) {
        if (ovf > OVF_CAP) ovf = OVF_CAP;
        for (int k = 0; k < ovf; k++) {
            int e = g_ovf_edges[k];
            if (__ldg(&ei[N_EDGES_C + e]) == node) {
                int s = __ldg(&ei[e]);
                unsigned long long uu = __ldg(&x2u[(size_t)s * 32 + lane]);
                accf.x += __uint_as_float((unsigned)(uu & 0xffffffffull));
                accf.y += __uint_as_float((unsigned)(uu >> 32));
            }
        }
    }

    float2 xvf;
    xvf.x = __uint_as_float((unsigned)(xv & 0xffffffffull));
    xvf.y = __uint_as_float((unsigned)(xv >> 32));

    float2 o;
    o.x = fmaf(WEIGHT, accf.x, xvf.x);
    o.y = fmaf(WEIGHT, accf.y, xvf.y);
    out2[(size_t)node * 32 + lane] = o;

    // consume-and-reset this node's counter (after the read; same warp)
    if (lane == 0) g_count[node] = 0;
}

// -------------------- fallback path (unexpected shapes) --------------------
__global__ void appr_copy_kernel(const float4* __restrict__ x4,
                                 float4* __restrict__ out4, long long n_vec) {
    long long i = (long long)blockIdx.x * blockDim.x + threadIdx.x;
    long long stride = (long long)gridDim.x * blockDim.x;
    for (; i < n_vec; i += stride) out4[i] = x4[i];
}

__global__ void appr_scatter_kernel(const float4* __restrict__ x4,
                                    const int* __restrict__ edge_index,
                                    float* __restrict__ out, long long n_edges) {
    long long t = (long long)blockIdx.x * blockDim.x + threadIdx.x;
    long long edge = t >> 4;
    int c = (int)(t & 15);
    if (edge >= n_edges) return;
    int src = __ldg(&edge_index[edge]);
    int dst = __ldg(&edge_index[n_edges + edge]);
    float4 v = __ldg(&x4[(long long)src * D_VEC + c]);
    v.x *= WEIGHT; v.y *= WEIGHT; v.z *= WEIGHT; v.w *= WEIGHT;
    float* p = out + (long long)dst * D_FEAT + c * 4;
    asm volatile("red.global.add.v4.f32 [%0], {%1, %2, %3, %4};"
                 :: "l"(p), "f"(v.x), "f"(v.y), "f"(v.z), "f"(v.w)
                 : "memory");
}

// ---------------------------------------------------------------------------
extern "C" void kernel_launch(void* const* d_in, const int* in_sizes, int n_in,
                              void* d_out, int out_size) {
    const float* x = (const float*)d_in[0];
    const int* edge_index = (const int*)d_in[1];
    float* out = (float*)d_out;

    long long n_x = in_sizes[0];
    long long n_edges = in_sizes[1] / 2;
    long long n_nodes = n_x / D_FEAT;

    if (n_nodes == N_NODES_C && n_edges == N_EDGES_C) {
        // 1) bucket fill (4 edges/thread; E divisible by 4)
        appr_fill_kernel<<<(N_EDGES_C / 4 + 255) / 256, 256>>>(edge_index);
        // 2) aggregate: warp per node (also resets g_count)
        long long total_threads = (long long)N_NODES_C * 32;
        appr_aggregate_kernel<<<(unsigned)((total_threads + 255) / 256), 256>>>(
            (const unsigned long long*)x, (float2*)out, edge_index);
    } else {
        // fallback: copy + RED scatter (touches no persistent state)
        long long n_vec = n_x / 4;
        int blocks = (int)((n_vec + 255) / 256);
        if (blocks > 8192) blocks = 8192;
        appr_copy_kernel<<<blocks, 256>>>((const float4*)x, (float4*)out, n_vec);
        long long total_threads = n_edges * 16;
        appr_scatter_kernel<<<(unsigned)((total_threads + 255) / 256), 256>>>(
            (const float4*)x, edge_index, out, n_edges);
    }
}

// round 12
// speedup vs baseline: 1.0081x; 1.0081x over previous
#include <cuda_runtime.h>
#include <cstdint>

#define N_NODES_C 100000
#define N_EDGES_C 1600000
#define D_FEAT 64
#define D_VEC  (D_FEAT / 4)
#define CAP 64            // per-node bucket capacity (Poisson(16): P(>64) ~ 1e-20)
#define OVF_CAP 8192
#define WEIGHT 0.15f

// packed f32x2 add (Blackwell): one instruction adds two floats in a 64b pair
#define ADD_F32X2(out, a, b) \
    asm("add.rn.f32x2 %0, %1, %2;" : "=l"(out) : "l"(a), "l"(b))

// -------------------- device scratch (static, zero-initialized) ------------
// Invariants (hold on every call, for this fixed input):
//  * g_count[] is ZERO at entry (zero-init on call 1; aggregate resets after).
//  * bucket slots [deg(node), CAP) are NEVER written (deg identical each call),
//    so they stay zero forever -> reading them early is safe (offset 0 = row 0,
//    killed by the tail predicate).
// Bucket entries are PRE-SCALED BYTE OFFSETS (src * 256), so the aggregate's
// per-gather address math is a single wide add.
__device__ unsigned int g_bucket[(size_t)N_NODES_C * CAP];
__device__ int g_count[N_NODES_C];
__device__ int g_ovf_edges[OVF_CAP];
__device__ int g_ovf_count;

// -------------------- 1) bucket fill (4 edges per thread) ------------------
__global__ void appr_fill_kernel(const int* __restrict__ ei) {
    int t = blockIdx.x * blockDim.x + threadIdx.x;
    int e0 = t * 4;
    if (e0 >= N_EDGES_C) return;

    int4 src = *reinterpret_cast<const int4*>(ei + e0);
    int4 dst = *reinterpret_cast<const int4*>(ei + N_EDGES_C + e0);

    // 4 independent atomics in flight, then 4 writes (pre-scaled offsets)
    int p0 = atomicAdd(&g_count[dst.x], 1);
    int p1 = atomicAdd(&g_count[dst.y], 1);
    int p2 = atomicAdd(&g_count[dst.z], 1);
    int p3 = atomicAdd(&g_count[dst.w], 1);

    if (p0 < CAP) g_bucket[(size_t)dst.x * CAP + p0] = (unsigned)src.x << 8;
    else { int o = atomicAdd(&g_ovf_count, 1); if (o < OVF_CAP) g_ovf_edges[o] = e0; }
    if (p1 < CAP) g_bucket[(size_t)dst.y * CAP + p1] = (unsigned)src.y << 8;
    else { int o = atomicAdd(&g_ovf_count, 1); if (o < OVF_CAP) g_ovf_edges[o] = e0 + 1; }
    if (p2 < CAP) g_bucket[(size_t)dst.z * CAP + p2] = (unsigned)src.z << 8;
    else { int o = atomicAdd(&g_ovf_count, 1); if (o < OVF_CAP) g_ovf_edges[o] = e0 + 2; }
    if (p3 < CAP) g_bucket[(size_t)dst.w * CAP + p3] = (unsigned)src.w << 8;
    else { int o = atomicAdd(&g_ovf_count, 1); if (o < OVF_CAP) g_ovf_edges[o] = e0 + 3; }
}

// -------------------- 2) gather-side aggregate ------------------------------
// One warp per node, lane owns a float2 = one 64-bit f32x2 pack.
// Bucket entries are byte offsets: gather address = lane_base + off (one wide
// add). R7 loop structure (pipelined index prefetch, predicated tail), f32x2
// reduction tree, 6 blocks/SM.
__global__ void __launch_bounds__(256, 6)
appr_aggregate_kernel(const unsigned long long* __restrict__ x2u,
                      float2* __restrict__ out2,
                      const int* __restrict__ ei) {
    int warp = (blockIdx.x * blockDim.x + threadIdx.x) >> 5;
    int lane = threadIdx.x & 31;
    if (warp >= N_NODES_C) return;
    int node = warp;

    const unsigned int* b = &g_bucket[(size_t)node * CAP];
    // per-lane base pointer: gathers become base + byte_off
    const char* xb = reinterpret_cast<const char*>(x2u) + lane * 8;

    // ---- concurrent prologue loads (all independent) ----
    uint4 s0 = *reinterpret_cast<const uint4*>(b);       // chunk-0 offsets
    uint4 s1 = *reinterpret_cast<const uint4*>(b + 4);   // (safe: slots >= deg are 0)
    int deg = g_count[node];
    unsigned long long xv = __ldg(&x2u[(size_t)node * 32 + lane]);   // own row

    int degc = deg > CAP ? CAP : deg;

    unsigned long long acc = 0ull;   // f32x2 {0.0f, 0.0f}

    if (degc > 0) {
        int j = 0;
        while (true) {
            uint4 c0 = s0, c1 = s1;
            int next = j + 8;
            if (next < degc) {
                // prefetch next chunk's offsets BEFORE this chunk's gathers
                s0 = *reinterpret_cast<const uint4*>(b + next);
                s1 = *reinterpret_cast<const uint4*>(b + next + 4);
            }

            if (next <= degc) {
                // full chunk: 8 unconditional gathers (base + byte offset)
                unsigned long long u0 = __ldg((const unsigned long long*)(xb + c0.x));
                unsigned long long u1 = __ldg((const unsigned long long*)(xb + c0.y));
                unsigned long long u2 = __ldg((const unsigned long long*)(xb + c0.z));
                unsigned long long u3 = __ldg((const unsigned long long*)(xb + c0.w));
                unsigned long long u4 = __ldg((const unsigned long long*)(xb + c1.x));
                unsigned long long u5 = __ldg((const unsigned long long*)(xb + c1.y));
                unsigned long long u6 = __ldg((const unsigned long long*)(xb + c1.z));
                unsigned long long u7 = __ldg((const unsigned long long*)(xb + c1.w));
                unsigned long long t01, t23, t45, t67, t03, t47, t07;
                ADD_F32X2(t01, u0, u1);
                ADD_F32X2(t23, u2, u3);
                ADD_F32X2(t45, u4, u5);
                ADD_F32X2(t67, u6, u7);
                ADD_F32X2(t03, t01, t23);
                ADD_F32X2(t47, t45, t67);
                ADD_F32X2(t07, t03, t47);
                ADD_F32X2(acc, acc, t07);
            } else {
                // partial last chunk: predicated gathers (offsets already loaded)
                int rem = degc - j;                     // 1..7
                unsigned int offs[8] = { c0.x, c0.y, c0.z, c0.w,
                                         c1.x, c1.y, c1.z, c1.w };
                unsigned long long u[8];
                #pragma unroll
                for (int k = 0; k < 8; k++) {
                    if (k < rem) u[k] = __ldg((const unsigned long long*)(xb + offs[k]));
                    else         u[k] = 0ull;
                }
                unsigned long long t01, t23, t45, t67, t03, t47, t07;
                ADD_F32X2(t01, u[0], u[1]);
                ADD_F32X2(t23, u[2], u[3]);
                ADD_F32X2(t45, u[4], u[5]);
                ADD_F32X2(t67, u[6], u[7]);
                ADD_F32X2(t03, t01, t23);
                ADD_F32X2(t47, t45, t67);
                ADD_F32X2(t07, t03, t47);
                ADD_F32X2(acc, acc, t07);
            }
            j = next;
            if (j >= degc) break;
        }
    }

    float2 accf;
    accf.x = __uint_as_float((unsigned)(acc & 0xffffffffull));
    accf.y = __uint_as_float((unsigned)(acc >> 32));

    // overflow contributions (g_ovf_count == 0 on this data: one broadcast ld)
    int ovf = g_ovf_count;
    if (ovf > 0) {
        if (ovf > OVF_CAP) ovf = OVF_CAP;
        for (int k = 0; k < ovf; k++) {
            int e = g_ovf_edges[k];
            if (__ldg(&ei[N_EDGES_C + e]) == node) {
                int s = __ldg(&ei[e]);
                unsigned long long uu = __ldg(&x2u[(size_t)s * 32 + lane]);
                accf.x += __uint_as_float((unsigned)(uu & 0xffffffffull));
                accf.y += __uint_as_float((unsigned)(uu >> 32));
            }
        }
    }

    float2 xvf;
    xvf.x = __uint_as_float((unsigned)(xv & 0xffffffffull));
    xvf.y = __uint_as_float((unsigned)(xv >> 32));

    float2 o;
    o.x = fmaf(WEIGHT, accf.x, xvf.x);
    o.y = fmaf(WEIGHT, accf.y, xvf.y);
    out2[(size_t)node * 32 + lane] = o;

    // consume-and-reset this node's counter (after the read; same warp)
    if (lane == 0) g_count[node] = 0;
}

// -------------------- fallback path (unexpected shapes) --------------------
__global__ void appr_copy_kernel(const float4* __restrict__ x4,
                                 float4* __restrict__ out4, long long n_vec) {
    long long i = (long long)blockIdx.x * blockDim.x + threadIdx.x;
    long long stride = (long long)gridDim.x * blockDim.x;
    for (; i < n_vec; i += stride) out4[i] = x4[i];
}

__global__ void appr_scatter_kernel(const float4* __restrict__ x4,
                                    const int* __restrict__ edge_index,
                                    float* __restrict__ out, long long n_edges) {
    long long t = (long long)blockIdx.x * blockDim.x + threadIdx.x;
    long long edge = t >> 4;
    int c = (int)(t & 15);
    if (edge >= n_edges) return;
    int src = __ldg(&edge_index[edge]);
    int dst = __ldg(&edge_index[n_edges + edge]);
    float4 v = __ldg(&x4[(long long)src * D_VEC + c]);
    v.x *= WEIGHT; v.y *= WEIGHT; v.z *= WEIGHT; v.w *= WEIGHT;
    float* p = out + (long long)dst * D_FEAT + c * 4;
    asm volatile("red.global.add.v4.f32 [%0], {%1, %2, %3, %4};"
                 :: "l"(p), "f"(v.x), "f"(v.y), "f"(v.z), "f"(v.w)
                 : "memory");
}

// ---------------------------------------------------------------------------
extern "C" void kernel_launch(void* const* d_in, const int* in_sizes, int n_in,
                              void* d_out, int out_size) {
    const float* x = (const float*)d_in[0];
    const int* edge_index = (const int*)d_in[1];
    float* out = (float*)d_out;

    long long n_x = in_sizes[0];
    long long n_edges = in_sizes[1] / 2;
    long long n_nodes = n_x / D_FEAT;

    if (n_nodes == N_NODES_C && n_edges == N_EDGES_C) {
        // 1) bucket fill (4 edges/thread; E divisible by 4)
        appr_fill_kernel<<<(N_EDGES_C / 4 + 255) / 256, 256>>>(edge_index);
        // 2) aggregate: warp per node (also resets g_count)
        long long total_threads = (long long)N_NODES_C * 32;
        appr_aggregate_kernel<<<(unsigned)((total_threads + 255) / 256), 256>>>(
            (const unsigned long long*)x, (float2*)out, edge_index);
    } else {
        // fallback: copy + RED scatter (touches no persistent state)
        long long n_vec = n_x / 4;
        int blocks = (int)((n_vec + 255) / 256);
        if (blocks > 8192) blocks = 8192;
        appr_copy_kernel<<<blocks, 256>>>((const float4*)x, (float4*)out, n_vec);
        long long total_threads = n_edges * 16;
        appr_scatter_kernel<<<(unsigned)((total_threads + 255) / 256), 256>>>(
            (const float4*)x, edge_index, out, n_edges);
    }
}